// round 9
// baseline (speedup 1.0000x reference)
#include <cuda_runtime.h>
#include <cuda_fp16.h>
#include <cstdint>

// out[65536,64] = xa[65536,256]@wa[256,64] + xb[65536,256]@wb[256,64]
// fp16 two-term scheme: A split (xh + xl, both fp16), B single fp16.
// mma.sync.m16n8k16.f32.f16.f16.f32. rel_err ~2e-4.
// B: read straight from L2-resident 64 KB fragment image (one use per CTA,
//    warp-contiguous 256B per (t,ni) -> cheap coalesced LDG.64).
// A: 4-stage cp.async ring, KC=16, row-stride 24 floats (conflict-free LDS).
// smem = 48 KB/CTA only -> 3 CTAs/SM (24 warps), launch_bounds(256,3).

#define M_TILE  128
#define NCHUNK  32                    // 32 chunks of 16 k
#define ASTRIDE 24                    // floats per smem A row (96 B)
#define ASTAGE  (128 * ASTRIDE)       // 3072 floats = 12288 B per stage
#define NSTAGE  4
#define SMEM_BYTES (NSTAGE * ASTAGE * 4)   // 49152

// fragment-packed B: index (t*8+ni)*32+L -> uint2 {b0,b1}, t = k-step 0..31
//   b0 = wh{k0,k0+1}, b1 = wh{k0+8,k0+9}; k0 = t*16+(L&3)*2, n = ni*8+(L>>2)
__device__ __align__(16) uint2 g_wfrag[32 * 8 * 32];   // 64 KB

__device__ __forceinline__ uint32_t h2pack(float lo, float hi) {
    uint32_t r;
    asm("cvt.rn.f16x2.f32 %0, %1, %2;" : "=r"(r) : "f"(hi), "f"(lo));
    return r;
}

__device__ __forceinline__ void h2unpack(uint32_t p, float& lo, float& hi) {
    asm("{ .reg .b16 l, h; mov.b32 {l, h}, %2;\n\t"
        "cvt.f32.f16 %0, l; cvt.f32.f16 %1, h; }"
        : "=f"(lo), "=f"(hi) : "r"(p));
}

__device__ __forceinline__ void split2h(float x0, float x1,
                                        uint32_t& hp, uint32_t& lp) {
    hp = h2pack(x0, x1);
    float h0, h1;
    h2unpack(hp, h0, h1);
    lp = h2pack(x0 - h0, x1 - h1);
}

__device__ __forceinline__ void mma16816(float* c, const uint32_t* a,
                                         uint32_t b0, uint32_t b1) {
    asm volatile(
        "mma.sync.aligned.m16n8k16.row.col.f32.f16.f16.f32 "
        "{%0,%1,%2,%3}, {%4,%5,%6,%7}, {%8,%9}, {%0,%1,%2,%3};"
        : "+f"(c[0]), "+f"(c[1]), "+f"(c[2]), "+f"(c[3])
        : "r"(a[0]), "r"(a[1]), "r"(a[2]), "r"(a[3]), "r"(b0), "r"(b1));
}

__device__ __forceinline__ uint32_t smem_u32(const void* p) {
    uint32_t a;
    asm("{ .reg .u64 t; cvta.to.shared.u64 t, %1; cvt.u32.u64 %0, t; }"
        : "=r"(a) : "l"(p));
    return a;
}

// ---- pre-kernel: pack fp16(w) into fragment order ----
__global__ void wconv_kernel(const float* __restrict__ wa,
                             const float* __restrict__ wb) {
    int id = blockIdx.x * 256 + threadIdx.x;   // 0..8191
    int L  = id & 31;
    int ni = (id >> 5) & 7;
    int t  = id >> 8;                          // k-step 0..31
    int k0 = t * 16 + (L & 3) * 2;             // global k
    int n  = ni * 8 + (L >> 2);
    const float* __restrict__ w = (k0 < 256) ? wa : wb;
    int kk = k0 & 255;
    float v0 = w[kk * 64 + n];
    float v1 = w[(kk + 1) * 64 + n];
    float v8 = w[(kk + 8) * 64 + n];
    float v9 = w[(kk + 9) * 64 + n];
    g_wfrag[id] = make_uint2(h2pack(v0, v1), h2pack(v8, v9));
}

// ---- main kernel ----
__global__ void __launch_bounds__(256, 3)
sshe_mma_kernel(const float* __restrict__ xa, const float* __restrict__ xb,
                float* __restrict__ out) {
    extern __shared__ float sA[];                 // 4-stage A ring
    const uint32_t sA_u = smem_u32(sA);
    const int tid = threadIdx.x;
    const int L = tid & 31;
    const int wid = tid >> 5;

    // cp.async coords: thread t -> row = t>>1, 2 x 16B (halves of 64B row)
    const int ld_row = tid >> 1;
    const int ld_h = (tid & 1) * 8;               // float offset 0 or 8
    const long long row0 = (long long)blockIdx.x * M_TILE;

    auto issue_chunk = [&](int c, int s) {
        const float* __restrict__ xsrc = (c < 16) ? xa : xb;
        const float* g = xsrc + (size_t)(row0 + ld_row) * 256 + (c & 15) * 16 +
                         ld_h;
        uint32_t d = sA_u +
                     (uint32_t)(s * ASTAGE + ld_row * ASTRIDE + ld_h) * 4;
        asm volatile("cp.async.cg.shared.global [%0], [%1], 16;"
                     :: "r"(d), "l"(g) : "memory");
        asm volatile("cp.async.cg.shared.global [%0], [%1], 16;"
                     :: "r"(d + 16), "l"(g + 4) : "memory");
    };

    // fragment coordinates (proven mapping)
    const int frow = wid * 16 + (L >> 2);
    const int kk2 = (L & 3) * 2;

    float acc[8][4];
#pragma unroll
    for (int i = 0; i < 8; i++)
#pragma unroll
        for (int j = 0; j < 4; j++) acc[i][j] = 0.f;

    // prologue: 3 stages in flight
#pragma unroll
    for (int c = 0; c < 3; c++) {
        issue_chunk(c, c);
        asm volatile("cp.async.commit_group;" ::: "memory");
    }

    const uint2* __restrict__ Bg = g_wfrag;

    for (int c = 0; c < NCHUNK; c++) {
        const int s = c & 3;
        asm volatile("cp.async.wait_group 2;" ::: "memory");
        __syncthreads();   // chunk c ready; slot (c+3)&3 free for reuse

        if (c + 3 < NCHUNK) issue_chunk(c + 3, (c + 3) & 3);
        asm volatile("cp.async.commit_group;" ::: "memory");

        // B fragments straight from global (L2-resident), issued early
        uint2 B[8];
        const int base = c * 256 + L;
#pragma unroll
        for (int ni = 0; ni < 8; ni++) B[ni] = __ldg(&Bg[base + ni * 32]);

        const float* A0 = sA + s * ASTAGE + frow * ASTRIDE + kk2;
        const float* A1 = A0 + 8 * ASTRIDE;
        float2 d0 = *(const float2*)(A0);
        float2 d1 = *(const float2*)(A1);
        float2 d2 = *(const float2*)(A0 + 8);
        float2 d3 = *(const float2*)(A1 + 8);
        uint32_t ah[4], al[4];
        split2h(d0.x, d0.y, ah[0], al[0]);
        split2h(d1.x, d1.y, ah[1], al[1]);
        split2h(d2.x, d2.y, ah[2], al[2]);
        split2h(d3.x, d3.y, ah[3], al[3]);

#pragma unroll
        for (int ni = 0; ni < 8; ni++) {
            mma16816(acc[ni], ah, B[ni].x, B[ni].y);   // xh * wh
            mma16816(acc[ni], al, B[ni].x, B[ni].y);   // xl * wh
        }
    }

    // epilogue (proven): c0,c1 -> (row, ni*8+kk2+{0,1}); c2,c3 -> (row+8, ..)
    const size_t grow = row0 + frow;
#pragma unroll
    for (int ni = 0; ni < 8; ni++) {
        float* o0 = out + grow * 64 + ni * 8 + kk2;
        float* o1 = out + (grow + 8) * 64 + ni * 8 + kk2;
        *(float2*)o0 = make_float2(acc[ni][0], acc[ni][1]);
        *(float2*)o1 = make_float2(acc[ni][2], acc[ni][3]);
    }
}

extern "C" void kernel_launch(void* const* d_in, const int* in_sizes, int n_in,
                              void* d_out, int out_size) {
    const float* xa = (const float*)d_in[0];
    const float* xb = (const float*)d_in[1];
    const float* wa = (const float*)d_in[2];
    const float* wb = (const float*)d_in[3];
    float* out = (float*)d_out;

    cudaFuncSetAttribute(sshe_mma_kernel,
                         cudaFuncAttributeMaxDynamicSharedMemorySize,
                         SMEM_BYTES);

    wconv_kernel<<<32, 256>>>(wa, wb);

    const int batch = in_sizes[0] / 256;     // 65536
    sshe_mma_kernel<<<batch / M_TILE, 256, SMEM_BYTES>>>(xa, xb, out);
}

// round 10
// speedup vs baseline: 1.1763x; 1.1763x over previous
#include <cuda_runtime.h>
#include <cuda_fp16.h>
#include <cstdint>

// out[65536,64] = xa[65536,256]@wa[256,64] + xb[65536,256]@wb[256,64]
// fp16 two-term scheme: A split (xh + xl, both fp16), B single fp16.
// mma.sync.m16n8k16.f32.f16.f16.f32. rel_err ~2e-4 (bit-identical to R5).
// A: coalesced LDG.128 (full-line, 4 wf/instr) -> reg split -> warp-private
//    smem stage (80B rows) -> ldmatrix.x4 fragments. __syncwarp only.
// B: pre-packed 64 KB fragment image in smem (proven path).
// CTA: 128 rows x 64 cols, 8 warps, 2 CTAs/SM, no CTA barriers in main loop.

#define M_TILE  128
#define NCHUNK  16                 // chunks of 32 k
#define SROW    80                 // stage row stride bytes (ldmatrix-safe)
#define PLANE   1280               // 16 rows * 80 B
#define WSTAGE  (4 * PLANE)        // 2 stages x 2 planes = 5120 B per warp
#define B_OFF   (8 * WSTAGE)       // 40960
#define SMEM_BYTES (B_OFF + 65536) // 106496

// fragment-packed B: index (t*8+ni)*32+L -> uint2 {b0,b1}, t = k-step 0..31
//   b0 = wh{k0,k0+1}, b1 = wh{k0+8,k0+9}; k0 = t*16+(L&3)*2, n = ni*8+(L>>2)
__device__ __align__(16) uint2 g_wfrag[32 * 8 * 32];   // 64 KB

__device__ __forceinline__ uint32_t h2pack(float lo, float hi) {
    uint32_t r;
    asm("cvt.rn.f16x2.f32 %0, %1, %2;" : "=r"(r) : "f"(hi), "f"(lo));
    return r;
}

__device__ __forceinline__ void h2unpack(uint32_t p, float& lo, float& hi) {
    asm("{ .reg .b16 l, h; mov.b32 {l, h}, %2;\n\t"
        "cvt.f32.f16 %0, l; cvt.f32.f16 %1, h; }"
        : "=f"(lo), "=f"(hi) : "r"(p));
}

__device__ __forceinline__ void split2h(float x0, float x1,
                                        uint32_t& hp, uint32_t& lp) {
    hp = h2pack(x0, x1);
    float h0, h1;
    h2unpack(hp, h0, h1);
    lp = h2pack(x0 - h0, x1 - h1);
}

__device__ __forceinline__ void mma16816(float* c, const uint32_t* a,
                                         uint32_t b0, uint32_t b1) {
    asm volatile(
        "mma.sync.aligned.m16n8k16.row.col.f32.f16.f16.f32 "
        "{%0,%1,%2,%3}, {%4,%5,%6,%7}, {%8,%9}, {%0,%1,%2,%3};"
        : "+f"(c[0]), "+f"(c[1]), "+f"(c[2]), "+f"(c[3])
        : "r"(a[0]), "r"(a[1]), "r"(a[2]), "r"(a[3]), "r"(b0), "r"(b1));
}

__device__ __forceinline__ void ldm4(uint32_t* r, uint32_t addr) {
    asm volatile("ldmatrix.sync.aligned.m8n8.x4.shared.b16 {%0,%1,%2,%3}, [%4];"
                 : "=r"(r[0]), "=r"(r[1]), "=r"(r[2]), "=r"(r[3]) : "r"(addr));
}

__device__ __forceinline__ uint32_t smem_u32(const void* p) {
    uint32_t a;
    asm("{ .reg .u64 t; cvta.to.shared.u64 t, %1; cvt.u32.u64 %0, t; }"
        : "=r"(a) : "l"(p));
    return a;
}

// ---- pre-kernel: pack fp16(w) into fragment order (unchanged, proven) ----
__global__ void wconv_kernel(const float* __restrict__ wa,
                             const float* __restrict__ wb) {
    int id = blockIdx.x * 256 + threadIdx.x;   // 0..8191
    int L  = id & 31;
    int ni = (id >> 5) & 7;
    int t  = id >> 8;                          // k-step 0..31
    int k0 = t * 16 + (L & 3) * 2;             // global k
    int n  = ni * 8 + (L >> 2);
    const float* __restrict__ w = (k0 < 256) ? wa : wb;
    int kk = k0 & 255;
    float v0 = w[kk * 64 + n];
    float v1 = w[(kk + 1) * 64 + n];
    float v8 = w[(kk + 8) * 64 + n];
    float v9 = w[(kk + 9) * 64 + n];
    g_wfrag[id] = make_uint2(h2pack(v0, v1), h2pack(v8, v9));
}

// ---- main kernel ----
__global__ void __launch_bounds__(256, 2)
sshe_mma_kernel(const float* __restrict__ xa, const float* __restrict__ xb,
                float* __restrict__ out) {
    extern __shared__ uint8_t smem[];          // [8 warp stages][B image]
    uint2* sB = (uint2*)(smem + B_OFF);
    const uint32_t sbase = smem_u32(smem);
    const int tid = threadIdx.x;
    const int L = tid & 31;
    const int wid = tid >> 5;

    // copy B fragments to smem (identity layout)
    {
        const uint4* src = (const uint4*)g_wfrag;
        uint4* dst = (uint4*)sB;
#pragma unroll
        for (int i = 0; i < 16; i++) dst[tid + i * 256] = src[tid + i * 256];
    }

    const long long row0 = (long long)blockIdx.x * M_TILE;

    // coalesced LDG coords: instr i covers rows 4i..4i+3 fully (1 line/row)
    const int lrow = L >> 3;                   // 0..3
    const int lf = (L & 7) * 4;                // float offset in 32-float chunk
    uint8_t* const wstage = smem + wid * WSTAGE;
    const uint32_t sts_off = (uint32_t)(lrow * SROW + (L & 7) * 8);
    // ldmatrix per-lane address offset within a plane
    const uint32_t ldm_off = (uint32_t)((L & 15) * SROW + (L >> 4) * 16);
    const uint32_t abase0 = sbase + (uint32_t)(wid * WSTAGE) + ldm_off;

    float acc[8][4];
#pragma unroll
    for (int i = 0; i < 8; i++)
#pragma unroll
        for (int j = 0; j < 4; j++) acc[i][j] = 0.f;

    float4 v[4];

    auto ldgc = [&](int c) {
        const float* __restrict__ xsrc = (c < 8) ? xa : xb;
        const float* p = xsrc + (size_t)(row0 + wid * 16 + lrow) * 256 +
                         (c & 7) * 32 + lf;
        v[0] = *(const float4*)(p);
        v[1] = *(const float4*)(p + 4 * 256);
        v[2] = *(const float4*)(p + 8 * 256);
        v[3] = *(const float4*)(p + 12 * 256);
    };

    auto stsc = [&](int s) {
        uint8_t* xh = wstage + s * (2 * PLANE);
        uint8_t* xl = xh + PLANE;
#pragma unroll
        for (int i = 0; i < 4; i++) {
            uint32_t h0, l0, h1, l1;
            split2h(v[i].x, v[i].y, h0, l0);
            split2h(v[i].z, v[i].w, h1, l1);
            uint32_t off = sts_off + (uint32_t)(i * 4 * SROW);
            *(uint2*)(xh + off) = make_uint2(h0, h1);
            *(uint2*)(xl + off) = make_uint2(l0, l1);
        }
    };

    // prologue: stage chunk 0; B image barrier
    ldgc(0);
    stsc(0);
    __syncwarp();
    __syncthreads();   // B image visible CTA-wide (only CTA barrier)

    for (int c = 0; c < NCHUNK; c++) {
        const int s = c & 1;
        if (c + 1 < NCHUNK) ldgc(c + 1);   // prefetch, lands during compute

        const uint32_t ab = abase0 + (uint32_t)(s * 2 * PLANE);
#pragma unroll
        for (int ks = 0; ks < 2; ks++) {
            uint32_t ah[4], al[4];
            ldm4(ah, ab + (uint32_t)(ks * 32));
            ldm4(al, ab + (uint32_t)(PLANE + ks * 32));
            const int bb = (c * 2 + ks) * 256 + L;
#pragma unroll
            for (int ni = 0; ni < 8; ni++) {
                uint2 B = sB[bb + ni * 32];
                mma16816(acc[ni], ah, B.x, B.y);   // xh * wh
                mma16816(acc[ni], al, B.x, B.y);   // xl * wh
            }
        }

        if (c + 1 < NCHUNK) {
            stsc(s ^ 1);
            __syncwarp();
        }
    }

    // epilogue (proven): c0,c1 -> (row, ni*8+kk2+{0,1}); c2,c3 -> (row+8, ..)
    const int frow = wid * 16 + (L >> 2);
    const int kk2 = (L & 3) * 2;
    const size_t grow = row0 + frow;
#pragma unroll
    for (int ni = 0; ni < 8; ni++) {
        float* o0 = out + grow * 64 + ni * 8 + kk2;
        float* o1 = out + (grow + 8) * 64 + ni * 8 + kk2;
        *(float2*)o0 = make_float2(acc[ni][0], acc[ni][1]);
        *(float2*)o1 = make_float2(acc[ni][2], acc[ni][3]);
    }
}

extern "C" void kernel_launch(void* const* d_in, const int* in_sizes, int n_in,
                              void* d_out, int out_size) {
    const float* xa = (const float*)d_in[0];
    const float* xb = (const float*)d_in[1];
    const float* wa = (const float*)d_in[2];
    const float* wb = (const float*)d_in[3];
    float* out = (float*)d_out;

    cudaFuncSetAttribute(sshe_mma_kernel,
                         cudaFuncAttributeMaxDynamicSharedMemorySize,
                         SMEM_BYTES);

    wconv_kernel<<<32, 256>>>(wa, wb);

    const int batch = in_sizes[0] / 256;     // 65536
    sshe_mma_kernel<<<batch / M_TILE, 256, SMEM_BYTES>>>(xa, xb, out);
}